// round 5
// baseline (speedup 1.0000x reference)
#include <cuda_runtime.h>
#include <cuda_bf16.h>
#include <cstdint>

#define NU 500000
#define NI 100000
#define FDIM 300
#define D 64
#define NE 2000000
#define EL 1000000

// ---------------- scratch (static device globals; allocation-free) ----------
__device__ float g_xitem[NI * D];
__device__ float g_deg_u[NU];
__device__ float g_deg_i[NI];
__device__ float g_acc_u[(size_t)NU * D];
__device__ float g_acc_i[(size_t)NI * D];
__device__ float g_hu[(size_t)NU * D];
__device__ float g_hi[(size_t)NI * D];
__device__ float g_hu2[(size_t)NU * D];
__device__ float g_hi2[(size_t)NI * D];

// ---------------- kernels ---------------------------------------------------

__global__ void zero_kernel(float4* __restrict__ p, size_t n4) {
    size_t i = (size_t)blockIdx.x * blockDim.x + threadIdx.x;
    size_t stride = (size_t)gridDim.x * blockDim.x;
    float4 z = make_float4(0.f, 0.f, 0.f, 0.f);
    for (; i < n4; i += stride) p[i] = z;
}

__global__ void degree_kernel(const int* __restrict__ src, const int* __restrict__ dst,
                              float* __restrict__ deg_u, float* __restrict__ deg_i) {
    int e = blockIdx.x * blockDim.x + threadIdx.x;
    if (e >= NE) return;
    atomicAdd(&deg_u[src[e]], 1.0f);
    atomicAdd(&deg_i[dst[e]], 1.0f);
}

// C[NI][64] = A[NI][300] @ B[300][64] + bias
__global__ void item_linear_kernel(const float* __restrict__ A, const float* __restrict__ B,
                                   const float* __restrict__ bias, float* __restrict__ C) {
    __shared__ float As[64][17];   // pad to dodge bank conflicts
    __shared__ float Bs[16][64];
    int row0 = blockIdx.x * 64;
    int col  = threadIdx.x & 63;
    int rgrp = threadIdx.x >> 6;   // 0..3
    float acc[16];
#pragma unroll
    for (int r = 0; r < 16; r++) acc[r] = 0.f;

    for (int kt = 0; kt < FDIM; kt += 16) {
        int kk = FDIM - kt; if (kk > 16) kk = 16;
        for (int i = threadIdx.x; i < 64 * 16; i += 256) {
            int r = i >> 4, k = i & 15;
            As[r][k] = (k < kk && (row0 + r) < NI) ? A[(size_t)(row0 + r) * FDIM + kt + k] : 0.f;
        }
        for (int i = threadIdx.x; i < 16 * 64; i += 256) {
            int k = i >> 6, c = i & 63;
            Bs[k][c] = (k < kk) ? B[(kt + k) * 64 + c] : 0.f;
        }
        __syncthreads();
#pragma unroll
        for (int k = 0; k < 16; k++) {
            float b = Bs[k][col];
#pragma unroll
            for (int r = 0; r < 16; r++)
                acc[r] += As[rgrp + 4 * r][k] * b;
        }
        __syncthreads();
    }
    float bv = bias[col];
#pragma unroll
    for (int r = 0; r < 16; r++) {
        int row = row0 + rgrp + 4 * r;
        if (row < NI) C[(size_t)row * 64 + col] = acc[r] + bv;
    }
}

// Both aggregation directions in one pass. 16 lanes per edge, float4 vector REDs.
__global__ void aggregate_kernel(const float* __restrict__ xu, const float* __restrict__ xi,
                                 const int* __restrict__ src, const int* __restrict__ dst,
                                 float* __restrict__ acc_u, float* __restrict__ acc_i) {
    int gt = blockIdx.x * blockDim.x + threadIdx.x;
    int e = gt >> 4;
    int l = (gt & 15) * 4;
    if (e >= NE) return;
    int s = __ldg(&src[e]);
    int d = __ldg(&dst[e]);
    float4 vu = *(const float4*)&xu[(size_t)s * 64 + l];
    atomicAdd((float4*)&acc_i[(size_t)d * 64 + l], vu);
    float4 vi = *(const float4*)&xi[(size_t)d * 64 + l];
    atomicAdd((float4*)&acc_u[(size_t)s * 64 + l], vi);
}

// out[n][j] = (acc[n]/max(deg,1)) @ Wl + b + x[n] @ Wr  (optional ReLU)
template <bool RELU>
__global__ void node_update_kernel(const float* __restrict__ acc, const float* __restrict__ deg,
                                   const float* __restrict__ x,
                                   const float* __restrict__ Wl, const float* __restrict__ Wr,
                                   const float* __restrict__ bias,
                                   float* __restrict__ out, int n) {
    __shared__ float sWl[64 * 64];
    __shared__ float sWr[64 * 64];
    __shared__ float sb[64];
    __shared__ float sagg[4][64];
    __shared__ float sx[4][64];
    for (int i = threadIdx.x; i < 4096; i += 256) { sWl[i] = Wl[i]; sWr[i] = Wr[i]; }
    if (threadIdx.x < 64) sb[threadIdx.x] = bias[threadIdx.x];
    __syncthreads();

    int col = threadIdx.x & 63;
    int nr  = threadIdx.x >> 6;          // 0..3
    int base = blockIdx.x * 64;
    for (int it = 0; it < 64; it += 4) {
        int node = base + it + nr;
        __syncthreads();                  // protect previous iteration's sagg/sx reads
        if (node < n) {
            float invd = 1.0f / fmaxf(deg[node], 1.0f);
            sagg[nr][col] = acc[(size_t)node * 64 + col] * invd;
            sx[nr][col]   = x[(size_t)node * 64 + col];
        }
        __syncthreads();
        if (node < n) {
            float a = sb[col];
#pragma unroll
            for (int k = 0; k < 64; k++)
                a += sagg[nr][k] * sWl[k * 64 + col] + sx[nr][k] * sWr[k * 64 + col];
            if (RELU) a = fmaxf(a, 0.f);
            out[(size_t)node * 64 + col] = a;
        }
    }
}

// out[e] = dot(hu[ls[e]], hi[ld[e]])  — warp per edge
__global__ void dot_kernel(const float* __restrict__ hu, const float* __restrict__ hi,
                           const int* __restrict__ ls, const int* __restrict__ ld,
                           float* __restrict__ out) {
    int e = blockIdx.x * (blockDim.x >> 5) + (threadIdx.x >> 5);
    int lane = threadIdx.x & 31;
    if (e >= EL) return;
    int s = __ldg(&ls[e]);
    int d = __ldg(&ld[e]);
    float2 a = *(const float2*)&hu[(size_t)s * 64 + lane * 2];
    float2 b = *(const float2*)&hi[(size_t)d * 64 + lane * 2];
    float v = a.x * b.x + a.y * b.y;
#pragma unroll
    for (int off = 16; off; off >>= 1) v += __shfl_down_sync(0xffffffffu, v, off);
    if (lane == 0) out[e] = v;
}

// ---------------- launcher --------------------------------------------------

extern "C" void kernel_launch(void* const* d_in, const int* in_sizes, int n_in,
                              void* d_out, int out_size) {
    const float* user_emb = (const float*)d_in[0];
    const float* item_x   = (const float*)d_in[1];
    const float* item_w   = (const float*)d_in[2];
    const float* item_b   = (const float*)d_in[3];
    const float* Wl1_ui = (const float*)d_in[4],  *Wr1_ui = (const float*)d_in[5],  *b1_ui = (const float*)d_in[6];
    const float* Wl1_iu = (const float*)d_in[7],  *Wr1_iu = (const float*)d_in[8],  *b1_iu = (const float*)d_in[9];
    const float* Wl2_ui = (const float*)d_in[10], *Wr2_ui = (const float*)d_in[11], *b2_ui = (const float*)d_in[12];
    const float* Wl2_iu = (const float*)d_in[13], *Wr2_iu = (const float*)d_in[14], *b2_iu = (const float*)d_in[15];
    // d_in[16] = user_node_id (arange -> identity gather)
    const int* esrc = (const int*)d_in[17];
    const int* edst = (const int*)d_in[18];
    const int* lsrc = (const int*)d_in[19];
    const int* ldst = (const int*)d_in[20];
    float* out = (float*)d_out;

    float *p_xitem, *p_degu, *p_degi, *p_accu, *p_acci, *p_hu, *p_hi, *p_hu2, *p_hi2;
    cudaGetSymbolAddress((void**)&p_xitem, g_xitem);
    cudaGetSymbolAddress((void**)&p_degu,  g_deg_u);
    cudaGetSymbolAddress((void**)&p_degi,  g_deg_i);
    cudaGetSymbolAddress((void**)&p_accu,  g_acc_u);
    cudaGetSymbolAddress((void**)&p_acci,  g_acc_i);
    cudaGetSymbolAddress((void**)&p_hu,    g_hu);
    cudaGetSymbolAddress((void**)&p_hi,    g_hi);
    cudaGetSymbolAddress((void**)&p_hu2,   g_hu2);
    cudaGetSymbolAddress((void**)&p_hi2,   g_hi2);

    const int ZB = 256;
    // degrees + zero accumulators
    zero_kernel<<<512,  ZB>>>((float4*)p_degu, (size_t)NU / 4);
    zero_kernel<<<256,  ZB>>>((float4*)p_degi, (size_t)NI / 4);
    zero_kernel<<<2048, ZB>>>((float4*)p_accu, (size_t)NU * D / 4);
    zero_kernel<<<1024, ZB>>>((float4*)p_acci, (size_t)NI * D / 4);
    degree_kernel<<<(NE + 255) / 256, 256>>>(esrc, edst, p_degu, p_degi);

    // item input projection
    item_linear_kernel<<<(NI + 63) / 64, 256>>>(item_x, item_w, item_b, p_xitem);

    // layer 1
    aggregate_kernel<<<(NE + 15) / 16, 256>>>(user_emb, p_xitem, esrc, edst, p_accu, p_acci);
    node_update_kernel<true><<<(NU + 63) / 64, 256>>>(p_accu, p_degu, user_emb,
                                                      Wl1_iu, Wr1_iu, b1_iu, p_hu, NU);
    node_update_kernel<true><<<(NI + 63) / 64, 256>>>(p_acci, p_degi, p_xitem,
                                                      Wl1_ui, Wr1_ui, b1_ui, p_hi, NI);

    // layer 2
    zero_kernel<<<2048, ZB>>>((float4*)p_accu, (size_t)NU * D / 4);
    zero_kernel<<<1024, ZB>>>((float4*)p_acci, (size_t)NI * D / 4);
    aggregate_kernel<<<(NE + 15) / 16, 256>>>(p_hu, p_hi, esrc, edst, p_accu, p_acci);
    node_update_kernel<false><<<(NU + 63) / 64, 256>>>(p_accu, p_degu, p_hu,
                                                       Wl2_iu, Wr2_iu, b2_iu, p_hu2, NU);
    node_update_kernel<false><<<(NI + 63) / 64, 256>>>(p_acci, p_degi, p_hi,
                                                       Wl2_ui, Wr2_ui, b2_ui, p_hi2, NI);

    // predictor
    dot_kernel<<<(EL + 7) / 8, 256>>>(p_hu2, p_hi2, lsrc, ldst, out);
}

// round 6
// speedup vs baseline: 2.0734x; 2.0734x over previous
#include <cuda_runtime.h>
#include <cuda_bf16.h>
#include <cstdint>

#define NU 500000
#define NI 100000
#define FDIM 300
#define D 64
#define NE 2000000
#define EL 1000000

// ---------------- scratch (static device globals; allocation-free) ----------
__device__ float g_xitem[(size_t)NI * D];
__device__ float g_acc_u[(size_t)NU * D];
__device__ float g_acc_i[(size_t)NI * D];
__device__ float g_hu [(size_t)NU * D];
__device__ float g_hi [(size_t)NI * D];
__device__ float g_hu2[(size_t)NU * D];
__device__ float g_hi2[(size_t)NI * D];

__device__ int g_degu[NU];
__device__ int g_degi[NI];
__device__ int g_offu[NU + 1];
__device__ int g_offi[NI + 1];
__device__ int g_curu[NU];
__device__ int g_curi[NI];
__device__ int g_bsu[512];
__device__ int g_bsi[512];
__device__ int g_nbru[NE];   // CSR by user: item neighbors
__device__ int g_nbri[NE];   // CSR by item: user neighbors

// ---------------- utility kernels -------------------------------------------

__global__ void zero_kernel(float4* __restrict__ p, size_t n4) {
    size_t i = (size_t)blockIdx.x * blockDim.x + threadIdx.x;
    size_t stride = (size_t)gridDim.x * blockDim.x;
    float4 z = make_float4(0.f, 0.f, 0.f, 0.f);
    for (; i < n4; i += stride) p[i] = z;
}

__global__ void count_kernel(const int* __restrict__ src, const int* __restrict__ dst,
                             int* __restrict__ du, int* __restrict__ di) {
    int e = blockIdx.x * blockDim.x + threadIdx.x;
    if (e >= NE) return;
    atomicAdd(&du[src[e]], 1);
    atomicAdd(&di[dst[e]], 1);
}

// block-level exclusive scan (1024 elems/block), emits block sums
__global__ void scan_block_k(const int* __restrict__ in, int* __restrict__ out,
                             int* __restrict__ bsum, int n) {
    __shared__ int sh[1024];
    int tid = threadIdx.x;
    int i = blockIdx.x * 1024 + tid;
    int v = (i < n) ? in[i] : 0;
    sh[tid] = v;
    __syncthreads();
    for (int off = 1; off < 1024; off <<= 1) {
        int t = (tid >= off) ? sh[tid - off] : 0;
        __syncthreads();
        sh[tid] += t;
        __syncthreads();
    }
    if (i < n) out[i] = sh[tid] - v;      // exclusive
    if (tid == 1023) bsum[blockIdx.x] = sh[1023];
}

// exclusive scan of up to 512 block sums, in place (single block)
__global__ void scan_sums_k(int* __restrict__ bsum, int nb) {
    __shared__ int sh[512];
    int tid = threadIdx.x;
    int v = (tid < nb) ? bsum[tid] : 0;
    sh[tid] = v;
    __syncthreads();
    for (int off = 1; off < 512; off <<= 1) {
        int t = (tid >= off) ? sh[tid - off] : 0;
        __syncthreads();
        sh[tid] += t;
        __syncthreads();
    }
    if (tid < nb) bsum[tid] = sh[tid] - v;
}

__global__ void add_off_k(int* __restrict__ offs, const int* __restrict__ bsum,
                          int n, int total) {
    int i = blockIdx.x * 1024 + threadIdx.x;
    if (i < n) offs[i] += bsum[i >> 10];
    else if (i == n) offs[n] = total;
}

__global__ void copy_int_k(const int* __restrict__ a, int* __restrict__ b, int n) {
    int i = blockIdx.x * blockDim.x + threadIdx.x;
    if (i < n) b[i] = a[i];
}

__global__ void build_csr_k(const int* __restrict__ src, const int* __restrict__ dst,
                            int* __restrict__ curu, int* __restrict__ curi,
                            int* __restrict__ nbru, int* __restrict__ nbri) {
    int e = blockIdx.x * blockDim.x + threadIdx.x;
    if (e >= NE) return;
    int s = src[e], d = dst[e];
    nbru[atomicAdd(&curu[s], 1)] = d;
    nbri[atomicAdd(&curi[d], 1)] = s;
}

// ---------------- item input linear ------------------------------------------
// C[NI][64] = A[NI][300] @ B[300][64] + bias
__global__ void item_linear_kernel(const float* __restrict__ A, const float* __restrict__ B,
                                   const float* __restrict__ bias, float* __restrict__ C) {
    __shared__ float As[64][17];
    __shared__ float Bs[16][64];
    int row0 = blockIdx.x * 64;
    int col  = threadIdx.x & 63;
    int rgrp = threadIdx.x >> 6;
    float acc[16];
#pragma unroll
    for (int r = 0; r < 16; r++) acc[r] = 0.f;

    for (int kt = 0; kt < FDIM; kt += 16) {
        int kk = FDIM - kt; if (kk > 16) kk = 16;
        for (int i = threadIdx.x; i < 64 * 16; i += 256) {
            int r = i >> 4, k = i & 15;
            As[r][k] = (k < kk && (row0 + r) < NI) ? A[(size_t)(row0 + r) * FDIM + kt + k] : 0.f;
        }
        for (int i = threadIdx.x; i < 16 * 64; i += 256) {
            int k = i >> 6, c = i & 63;
            Bs[k][c] = (k < kk) ? B[(kt + k) * 64 + c] : 0.f;
        }
        __syncthreads();
#pragma unroll
        for (int k = 0; k < 16; k++) {
            float b = Bs[k][col];
#pragma unroll
            for (int r = 0; r < 16; r++)
                acc[r] += As[rgrp + 4 * r][k] * b;
        }
        __syncthreads();
    }
    float bv = bias[col];
#pragma unroll
    for (int r = 0; r < 16; r++) {
        int row = row0 + rgrp + 4 * r;
        if (row < NI) C[(size_t)row * 64 + col] = acc[r] + bv;
    }
}

// ---------------- CSR aggregation (sum; mean applied in node update) ---------
__global__ void agg_csr_k(const float* __restrict__ xs, const int* __restrict__ offs,
                          const int* __restrict__ nbr, float* __restrict__ osum, int n) {
    int gt = blockIdx.x * blockDim.x + threadIdx.x;
    int node = gt >> 4;
    int l = (gt & 15) << 2;
    if (node >= n) return;
    int e = offs[node], end = offs[node + 1];
    float4 a = make_float4(0.f, 0.f, 0.f, 0.f);
    for (; e + 2 <= end; e += 2) {
        int s0 = __ldg(&nbr[e]);
        int s1 = __ldg(&nbr[e + 1]);
        float4 v0 = *(const float4*)&xs[(size_t)s0 * 64 + l];
        float4 v1 = *(const float4*)&xs[(size_t)s1 * 64 + l];
        a.x += v0.x + v1.x; a.y += v0.y + v1.y;
        a.z += v0.z + v1.z; a.w += v0.w + v1.w;
    }
    if (e < end) {
        int s0 = __ldg(&nbr[e]);
        float4 v0 = *(const float4*)&xs[(size_t)s0 * 64 + l];
        a.x += v0.x; a.y += v0.y; a.z += v0.z; a.w += v0.w;
    }
    *(float4*)&osum[(size_t)node * 64 + l] = a;
}

// ---------------- node update: register-tiled GEMM ---------------------------
// out[n][c] = (accsum[n]/deg) @ Wl + b + x[n] @ Wr   (optional ReLU)
// Block = 256 threads, tile = 64 nodes x 64 cols, thread = 4x4 register tile.
template <bool RELU>
__global__ __launch_bounds__(256) void node_update2(
    const float* __restrict__ accsum, const int* __restrict__ offs,
    const float* __restrict__ x,
    const float* __restrict__ Wl, const float* __restrict__ Wr,
    const float* __restrict__ bias, float* __restrict__ out, int n)
{
    __shared__ float sW[64][64];      // weights [k][col]
    __shared__ float sF[64][64];      // features transposed [k][node]
    int tid = threadIdx.x;
    int base = blockIdx.x * 64;
    int nl = tid & 63;                // node lane for feature staging
    int node = base + nl;
    bool valid = node < n;
    float invd = 1.0f;
    if (valid) {
        int beg = offs[node], end = offs[node + 1];
        invd = 1.0f / fmaxf((float)(end - beg), 1.0f);
    }
    int ni4 = (tid >> 4) << 2;        // node offset within tile (0..60)
    int cj4 = (tid & 15) << 2;        // col offset (0..60)

    float acc[4][4];
#pragma unroll
    for (int i = 0; i < 4; i++)
#pragma unroll
        for (int j = 0; j < 4; j++) acc[i][j] = 0.f;

#pragma unroll
    for (int pass = 0; pass < 2; pass++) {
        __syncthreads();
        // stage weights
        const float4* wsrc = (const float4*)(pass == 0 ? Wl : Wr);
        float4* wdst = (float4*)&sW[0][0];
        for (int i = tid; i < 1024; i += 256) wdst[i] = wsrc[i];
        // stage features transposed (scale agg by 1/deg)
        const float* fsrc = (pass == 0) ? accsum : x;
        float scale = (pass == 0) ? invd : 1.0f;
        for (int kq = tid >> 6; kq < 16; kq += 4) {
            float4 v = valid ? *(const float4*)&fsrc[(size_t)node * 64 + kq * 4]
                             : make_float4(0.f, 0.f, 0.f, 0.f);
            sF[kq * 4 + 0][nl] = v.x * scale;
            sF[kq * 4 + 1][nl] = v.y * scale;
            sF[kq * 4 + 2][nl] = v.z * scale;
            sF[kq * 4 + 3][nl] = v.w * scale;
        }
        __syncthreads();
#pragma unroll 16
        for (int k = 0; k < 64; k++) {
            float4 f = *(const float4*)&sF[k][ni4];
            float4 w = *(const float4*)&sW[k][cj4];
            acc[0][0] += f.x * w.x; acc[0][1] += f.x * w.y; acc[0][2] += f.x * w.z; acc[0][3] += f.x * w.w;
            acc[1][0] += f.y * w.x; acc[1][1] += f.y * w.y; acc[1][2] += f.y * w.z; acc[1][3] += f.y * w.w;
            acc[2][0] += f.z * w.x; acc[2][1] += f.z * w.y; acc[2][2] += f.z * w.z; acc[2][3] += f.z * w.w;
            acc[3][0] += f.w * w.x; acc[3][1] += f.w * w.y; acc[3][2] += f.w * w.z; acc[3][3] += f.w * w.w;
        }
    }

    float4 bv = *(const float4*)&bias[cj4];
#pragma unroll
    for (int i = 0; i < 4; i++) {
        int nd = base + ni4 + i;
        if (nd < n) {
            float4 o;
            o.x = acc[i][0] + bv.x;
            o.y = acc[i][1] + bv.y;
            o.z = acc[i][2] + bv.z;
            o.w = acc[i][3] + bv.w;
            if (RELU) {
                o.x = fmaxf(o.x, 0.f); o.y = fmaxf(o.y, 0.f);
                o.z = fmaxf(o.z, 0.f); o.w = fmaxf(o.w, 0.f);
            }
            *(float4*)&out[(size_t)nd * 64 + cj4] = o;
        }
    }
}

// ---------------- dot predictor: 16 lanes per edge, float4 -------------------
__global__ void dot_kernel16(const float* __restrict__ hu, const float* __restrict__ hi,
                             const int* __restrict__ ls, const int* __restrict__ ld,
                             float* __restrict__ out) {
    int gt = blockIdx.x * blockDim.x + threadIdx.x;
    int e = gt >> 4;
    int l = (gt & 15) << 2;
    if (e >= EL) return;
    int s = __ldg(&ls[e]);
    int d = __ldg(&ld[e]);
    float4 a = *(const float4*)&hu[(size_t)s * 64 + l];
    float4 b = *(const float4*)&hi[(size_t)d * 64 + l];
    float v = a.x * b.x + a.y * b.y + a.z * b.z + a.w * b.w;
    v += __shfl_down_sync(0xffffffffu, v, 8);
    v += __shfl_down_sync(0xffffffffu, v, 4);
    v += __shfl_down_sync(0xffffffffu, v, 2);
    v += __shfl_down_sync(0xffffffffu, v, 1);
    if ((gt & 15) == 0) out[e] = v;
}

// ---------------- launcher ---------------------------------------------------

extern "C" void kernel_launch(void* const* d_in, const int* in_sizes, int n_in,
                              void* d_out, int out_size) {
    const float* user_emb = (const float*)d_in[0];
    const float* item_x   = (const float*)d_in[1];
    const float* item_w   = (const float*)d_in[2];
    const float* item_b   = (const float*)d_in[3];
    const float* Wl1_ui = (const float*)d_in[4],  *Wr1_ui = (const float*)d_in[5],  *b1_ui = (const float*)d_in[6];
    const float* Wl1_iu = (const float*)d_in[7],  *Wr1_iu = (const float*)d_in[8],  *b1_iu = (const float*)d_in[9];
    const float* Wl2_ui = (const float*)d_in[10], *Wr2_ui = (const float*)d_in[11], *b2_ui = (const float*)d_in[12];
    const float* Wl2_iu = (const float*)d_in[13], *Wr2_iu = (const float*)d_in[14], *b2_iu = (const float*)d_in[15];
    // d_in[16] = user_node_id (arange -> identity gather)
    const int* esrc = (const int*)d_in[17];
    const int* edst = (const int*)d_in[18];
    const int* lsrc = (const int*)d_in[19];
    const int* ldst = (const int*)d_in[20];
    float* out = (float*)d_out;

    float *p_xitem, *p_accu, *p_acci, *p_hu, *p_hi, *p_hu2, *p_hi2;
    int *p_degu, *p_degi, *p_offu, *p_offi, *p_curu, *p_curi, *p_bsu, *p_bsi, *p_nbru, *p_nbri;
    cudaGetSymbolAddress((void**)&p_xitem, g_xitem);
    cudaGetSymbolAddress((void**)&p_accu,  g_acc_u);
    cudaGetSymbolAddress((void**)&p_acci,  g_acc_i);
    cudaGetSymbolAddress((void**)&p_hu,    g_hu);
    cudaGetSymbolAddress((void**)&p_hi,    g_hi);
    cudaGetSymbolAddress((void**)&p_hu2,   g_hu2);
    cudaGetSymbolAddress((void**)&p_hi2,   g_hi2);
    cudaGetSymbolAddress((void**)&p_degu,  g_degu);
    cudaGetSymbolAddress((void**)&p_degi,  g_degi);
    cudaGetSymbolAddress((void**)&p_offu,  g_offu);
    cudaGetSymbolAddress((void**)&p_offi,  g_offi);
    cudaGetSymbolAddress((void**)&p_curu,  g_curu);
    cudaGetSymbolAddress((void**)&p_curi,  g_curi);
    cudaGetSymbolAddress((void**)&p_bsu,   g_bsu);
    cudaGetSymbolAddress((void**)&p_bsi,   g_bsi);
    cudaGetSymbolAddress((void**)&p_nbru,  g_nbru);
    cudaGetSymbolAddress((void**)&p_nbri,  g_nbri);

    // ---- CSR build (once; reused by both layers) ----
    zero_kernel<<<512, 256>>>((float4*)p_degu, (size_t)NU / 4);
    zero_kernel<<<128, 256>>>((float4*)p_degi, (size_t)NI / 4);
    count_kernel<<<(NE + 255) / 256, 256>>>(esrc, edst, p_degu, p_degi);

    int nbu = (NU + 1023) / 1024;   // 489
    int nbi = (NI + 1023) / 1024;   // 98
    scan_block_k<<<nbu, 1024>>>(p_degu, p_offu, p_bsu, NU);
    scan_block_k<<<nbi, 1024>>>(p_degi, p_offi, p_bsi, NI);
    scan_sums_k<<<1, 512>>>(p_bsu, nbu);
    scan_sums_k<<<1, 512>>>(p_bsi, nbi);
    add_off_k<<<(NU + 1024) / 1024, 1024>>>(p_offu, p_bsu, NU, NE);
    add_off_k<<<(NI + 1024) / 1024, 1024>>>(p_offi, p_bsi, NI, NE);
    copy_int_k<<<(NU + 255) / 256, 256>>>(p_offu, p_curu, NU);
    copy_int_k<<<(NI + 255) / 256, 256>>>(p_offi, p_curi, NI);
    build_csr_k<<<(NE + 255) / 256, 256>>>(esrc, edst, p_curu, p_curi, p_nbru, p_nbri);

    // ---- item input projection ----
    item_linear_kernel<<<(NI + 63) / 64, 256>>>(item_x, item_w, item_b, p_xitem);

    // ---- layer 1 ----
    agg_csr_k<<<((size_t)NI * 16 + 255) / 256, 256>>>(user_emb, p_offi, p_nbri, p_acci, NI);
    agg_csr_k<<<((size_t)NU * 16 + 255) / 256, 256>>>(p_xitem,  p_offu, p_nbru, p_accu, NU);
    node_update2<true><<<(NU + 63) / 64, 256>>>(p_accu, p_offu, user_emb,
                                                Wl1_iu, Wr1_iu, b1_iu, p_hu, NU);
    node_update2<true><<<(NI + 63) / 64, 256>>>(p_acci, p_offi, p_xitem,
                                                Wl1_ui, Wr1_ui, b1_ui, p_hi, NI);

    // ---- layer 2 ----
    agg_csr_k<<<((size_t)NI * 16 + 255) / 256, 256>>>(p_hu, p_offi, p_nbri, p_acci, NI);
    agg_csr_k<<<((size_t)NU * 16 + 255) / 256, 256>>>(p_hi, p_offu, p_nbru, p_accu, NU);
    node_update2<false><<<(NU + 63) / 64, 256>>>(p_accu, p_offu, p_hu,
                                                 Wl2_iu, Wr2_iu, b2_iu, p_hu2, NU);
    node_update2<false><<<(NI + 63) / 64, 256>>>(p_acci, p_offi, p_hi,
                                                 Wl2_ui, Wr2_ui, b2_ui, p_hi2, NI);

    // ---- predictor ----
    dot_kernel16<<<((size_t)EL * 16 + 255) / 256, 256>>>(p_hu2, p_hi2, lsrc, ldst, out);
}

// round 7
// speedup vs baseline: 2.3690x; 1.1426x over previous
#include <cuda_runtime.h>
#include <cuda_bf16.h>
#include <cstdint>

#define NU 500000
#define NI 100000
#define FDIM 300
#define D 64
#define NE 2000000
#define EL 1000000

using u64 = unsigned long long;

__device__ __forceinline__ u64 pack2(float lo, float hi) {
    u64 r; asm("mov.b64 %0, {%1, %2};" : "=l"(r) : "f"(lo), "f"(hi)); return r;
}
__device__ __forceinline__ void fma2(u64& acc, u64 a, u64 b) {
    asm("fma.rn.f32x2 %0, %1, %2, %0;" : "+l"(acc) : "l"(a), "l"(b));
}
__device__ __forceinline__ float2 unpack2(u64 v) {
    float2 f; asm("mov.b64 {%0, %1}, %2;" : "=f"(f.x), "=f"(f.y) : "l"(v)); return f;
}

// ---------------- scratch (static device globals; allocation-free) ----------
__device__ float g_xitem[(size_t)NI * D];
__device__ float g_acc_u[(size_t)NU * D];
__device__ float g_acc_i[(size_t)NI * D];
__device__ float g_hu [(size_t)NU * D];
__device__ float g_hi [(size_t)NI * D];
__device__ float g_hu2[(size_t)NU * D];
__device__ float g_hi2[(size_t)NI * D];

__device__ int g_degu[NU];
__device__ int g_degi[NI];
__device__ int g_offu[NU + 1];
__device__ int g_offi[NI + 1];
__device__ int g_curu[NU];
__device__ int g_curi[NI];
__device__ int g_bsu[512];
__device__ int g_bsi[512];
__device__ int g_nbru[NE];   // CSR by user: item neighbors
__device__ int g_nbri[NE];   // CSR by item: user neighbors

// ---------------- utility kernels -------------------------------------------

__global__ void zero_kernel(float4* __restrict__ p, size_t n4) {
    size_t i = (size_t)blockIdx.x * blockDim.x + threadIdx.x;
    size_t stride = (size_t)gridDim.x * blockDim.x;
    float4 z = make_float4(0.f, 0.f, 0.f, 0.f);
    for (; i < n4; i += stride) p[i] = z;
}

__global__ void count_kernel(const int* __restrict__ src, const int* __restrict__ dst,
                             int* __restrict__ du, int* __restrict__ di) {
    int e = blockIdx.x * blockDim.x + threadIdx.x;
    if (e >= NE) return;
    atomicAdd(&du[src[e]], 1);
    atomicAdd(&di[dst[e]], 1);
}

__global__ void scan_block_k(const int* __restrict__ in, int* __restrict__ out,
                             int* __restrict__ bsum, int n) {
    __shared__ int sh[1024];
    int tid = threadIdx.x;
    int i = blockIdx.x * 1024 + tid;
    int v = (i < n) ? in[i] : 0;
    sh[tid] = v;
    __syncthreads();
    for (int off = 1; off < 1024; off <<= 1) {
        int t = (tid >= off) ? sh[tid - off] : 0;
        __syncthreads();
        sh[tid] += t;
        __syncthreads();
    }
    if (i < n) out[i] = sh[tid] - v;      // exclusive
    if (tid == 1023) bsum[blockIdx.x] = sh[1023];
}

__global__ void scan_sums_k(int* __restrict__ bsum, int nb) {
    __shared__ int sh[512];
    int tid = threadIdx.x;
    int v = (tid < nb) ? bsum[tid] : 0;
    sh[tid] = v;
    __syncthreads();
    for (int off = 1; off < 512; off <<= 1) {
        int t = (tid >= off) ? sh[tid - off] : 0;
        __syncthreads();
        sh[tid] += t;
        __syncthreads();
    }
    if (tid < nb) bsum[tid] = sh[tid] - v;
}

__global__ void add_off_k(int* __restrict__ offs, const int* __restrict__ bsum,
                          int n, int total) {
    int i = blockIdx.x * 1024 + threadIdx.x;
    if (i < n) offs[i] += bsum[i >> 10];
    else if (i == n) offs[n] = total;
}

__global__ void copy_int_k(const int* __restrict__ a, int* __restrict__ b, int n) {
    int i = blockIdx.x * blockDim.x + threadIdx.x;
    if (i < n) b[i] = a[i];
}

__global__ void build_csr_k(const int* __restrict__ src, const int* __restrict__ dst,
                            int* __restrict__ curu, int* __restrict__ curi,
                            int* __restrict__ nbru, int* __restrict__ nbri) {
    int e = blockIdx.x * blockDim.x + threadIdx.x;
    if (e >= NE) return;
    int s = src[e], d = dst[e];
    nbru[atomicAdd(&curu[s], 1)] = d;
    nbri[atomicAdd(&curi[d], 1)] = s;
}

// ---------------- item input linear (register-tiled f32x2) -------------------
// C[NI][64] = A[NI][300] @ B[300][64] + bias
// Block tile: 64 rows x 64 cols, thread: 4x4, K in tiles of 60 (300 = 5*60).
__global__ __launch_bounds__(256) void item_linear2(
    const float* __restrict__ A, const float* __restrict__ B,
    const float* __restrict__ bias, float* __restrict__ C)
{
    __shared__ float sA[60 * 68];   // [k][row] transposed, padded stride 68
    __shared__ float sB[60 * 64];   // [k][col]
    int tid = threadIdx.x;
    int row0 = blockIdx.x * 64;
    int ni4 = (tid >> 4) << 2;      // row offset within tile (0..60)
    int cj4 = (tid & 15) << 2;      // col offset (0..60)

    u64 acc2[2][4];
#pragma unroll
    for (int ip = 0; ip < 2; ip++)
#pragma unroll
        for (int j = 0; j < 4; j++) acc2[ip][j] = 0ull;

    for (int kt = 0; kt < FDIM; kt += 60) {
        __syncthreads();
        // stage A transposed: sA[k][r] = A[row0+r][kt+k]
        for (int idx = tid; idx < 64 * 60; idx += 256) {
            int r = idx / 60;
            int k = idx - r * 60;
            int row = row0 + r;
            sA[k * 68 + r] = (row < NI) ? A[(size_t)row * FDIM + kt + k] : 0.f;
        }
        // stage B: sB[k][c]
        for (int idx = tid; idx < 60 * 64; idx += 256) {
            int k = idx >> 6, c = idx & 63;
            sB[idx] = B[(kt + k) * 64 + c];
        }
        __syncthreads();
#pragma unroll 12
        for (int k = 0; k < 60; k++) {
            float4 f = *(const float4*)&sA[k * 68 + ni4];
            float4 w = *(const float4*)&sB[k * 64 + cj4];
            u64 f01 = pack2(f.x, f.y);
            u64 f23 = pack2(f.z, f.w);
            u64 w0 = pack2(w.x, w.x), w1 = pack2(w.y, w.y);
            u64 w2 = pack2(w.z, w.z), w3 = pack2(w.w, w.w);
            fma2(acc2[0][0], f01, w0); fma2(acc2[0][1], f01, w1);
            fma2(acc2[0][2], f01, w2); fma2(acc2[0][3], f01, w3);
            fma2(acc2[1][0], f23, w0); fma2(acc2[1][1], f23, w1);
            fma2(acc2[1][2], f23, w2); fma2(acc2[1][3], f23, w3);
        }
    }

    float res[4][4];
#pragma unroll
    for (int ip = 0; ip < 2; ip++)
#pragma unroll
        for (int j = 0; j < 4; j++) {
            float2 t = unpack2(acc2[ip][j]);
            res[2 * ip][j] = t.x;
            res[2 * ip + 1][j] = t.y;
        }
    float4 bv = *(const float4*)&bias[cj4];
#pragma unroll
    for (int i = 0; i < 4; i++) {
        int row = row0 + ni4 + i;
        if (row < NI) {
            float4 o;
            o.x = res[i][0] + bv.x; o.y = res[i][1] + bv.y;
            o.z = res[i][2] + bv.z; o.w = res[i][3] + bv.w;
            *(float4*)&C[(size_t)row * 64 + cj4] = o;
        }
    }
}

// ---------------- CSR aggregation (sum; mean applied in node update) ---------
__global__ void agg_csr_k(const float* __restrict__ xs, const int* __restrict__ offs,
                          const int* __restrict__ nbr, float* __restrict__ osum, int n) {
    int gt = blockIdx.x * blockDim.x + threadIdx.x;
    int node = gt >> 4;
    int l = (gt & 15) << 2;
    if (node >= n) return;
    int e = offs[node], end = offs[node + 1];
    float4 a = make_float4(0.f, 0.f, 0.f, 0.f);
    for (; e + 2 <= end; e += 2) {
        int s0 = __ldg(&nbr[e]);
        int s1 = __ldg(&nbr[e + 1]);
        float4 v0 = *(const float4*)&xs[(size_t)s0 * 64 + l];
        float4 v1 = *(const float4*)&xs[(size_t)s1 * 64 + l];
        a.x += v0.x + v1.x; a.y += v0.y + v1.y;
        a.z += v0.z + v1.z; a.w += v0.w + v1.w;
    }
    if (e < end) {
        int s0 = __ldg(&nbr[e]);
        float4 v0 = *(const float4*)&xs[(size_t)s0 * 64 + l];
        a.x += v0.x; a.y += v0.y; a.z += v0.z; a.w += v0.w;
    }
    *(float4*)&osum[(size_t)node * 64 + l] = a;
}

// ---------------- node update: register-tiled f32x2 GEMM ---------------------
// out[n][c] = (accsum[n]/deg) @ Wl + b + x[n] @ Wr   (optional ReLU)
template <bool RELU>
__global__ __launch_bounds__(256) void node_update2(
    const float* __restrict__ accsum, const int* __restrict__ offs,
    const float* __restrict__ x,
    const float* __restrict__ Wl, const float* __restrict__ Wr,
    const float* __restrict__ bias, float* __restrict__ out, int n)
{
    __shared__ float sW[64][64];      // weights [k][col]
    __shared__ float sF[64][64];      // features transposed [k][node]
    int tid = threadIdx.x;
    int base = blockIdx.x * 64;
    int nl = tid & 63;                // node lane for feature staging
    int node = base + nl;
    bool valid = node < n;
    float invd = 1.0f;
    if (valid) {
        int beg = offs[node], end = offs[node + 1];
        invd = 1.0f / fmaxf((float)(end - beg), 1.0f);
    }
    int ni4 = (tid >> 4) << 2;        // node offset within tile (0..60)
    int cj4 = (tid & 15) << 2;        // col offset (0..60)

    u64 acc2[2][4];
#pragma unroll
    for (int ip = 0; ip < 2; ip++)
#pragma unroll
        for (int j = 0; j < 4; j++) acc2[ip][j] = 0ull;

#pragma unroll
    for (int pass = 0; pass < 2; pass++) {
        __syncthreads();
        const float4* wsrc = (const float4*)(pass == 0 ? Wl : Wr);
        float4* wdst = (float4*)&sW[0][0];
        for (int i = tid; i < 1024; i += 256) wdst[i] = wsrc[i];
        const float* fsrc = (pass == 0) ? accsum : x;
        float scale = (pass == 0) ? invd : 1.0f;
        for (int kq = tid >> 6; kq < 16; kq += 4) {
            float4 v = valid ? *(const float4*)&fsrc[(size_t)node * 64 + kq * 4]
                             : make_float4(0.f, 0.f, 0.f, 0.f);
            sF[kq * 4 + 0][nl] = v.x * scale;
            sF[kq * 4 + 1][nl] = v.y * scale;
            sF[kq * 4 + 2][nl] = v.z * scale;
            sF[kq * 4 + 3][nl] = v.w * scale;
        }
        __syncthreads();
#pragma unroll 16
        for (int k = 0; k < 64; k++) {
            float4 f = *(const float4*)&sF[k][ni4];
            float4 w = *(const float4*)&sW[k][cj4];
            u64 f01 = pack2(f.x, f.y);
            u64 f23 = pack2(f.z, f.w);
            u64 w0 = pack2(w.x, w.x), w1 = pack2(w.y, w.y);
            u64 w2 = pack2(w.z, w.z), w3 = pack2(w.w, w.w);
            fma2(acc2[0][0], f01, w0); fma2(acc2[0][1], f01, w1);
            fma2(acc2[0][2], f01, w2); fma2(acc2[0][3], f01, w3);
            fma2(acc2[1][0], f23, w0); fma2(acc2[1][1], f23, w1);
            fma2(acc2[1][2], f23, w2); fma2(acc2[1][3], f23, w3);
        }
    }

    float res[4][4];
#pragma unroll
    for (int ip = 0; ip < 2; ip++)
#pragma unroll
        for (int j = 0; j < 4; j++) {
            float2 t = unpack2(acc2[ip][j]);
            res[2 * ip][j] = t.x;
            res[2 * ip + 1][j] = t.y;
        }
    float4 bv = *(const float4*)&bias[cj4];
#pragma unroll
    for (int i = 0; i < 4; i++) {
        int nd = base + ni4 + i;
        if (nd < n) {
            float4 o;
            o.x = res[i][0] + bv.x;
            o.y = res[i][1] + bv.y;
            o.z = res[i][2] + bv.z;
            o.w = res[i][3] + bv.w;
            if (RELU) {
                o.x = fmaxf(o.x, 0.f); o.y = fmaxf(o.y, 0.f);
                o.z = fmaxf(o.z, 0.f); o.w = fmaxf(o.w, 0.f);
            }
            *(float4*)&out[(size_t)nd * 64 + cj4] = o;
        }
    }
}

// ---------------- dot predictor: 16 lanes per edge, float4 -------------------
__global__ void dot_kernel16(const float* __restrict__ hu, const float* __restrict__ hi,
                             const int* __restrict__ ls, const int* __restrict__ ld,
                             float* __restrict__ out) {
    int gt = blockIdx.x * blockDim.x + threadIdx.x;
    int e = gt >> 4;
    int l = (gt & 15) << 2;
    if (e >= EL) return;
    int s = __ldg(&ls[e]);
    int d = __ldg(&ld[e]);
    float4 a = *(const float4*)&hu[(size_t)s * 64 + l];
    float4 b = *(const float4*)&hi[(size_t)d * 64 + l];
    float v = a.x * b.x + a.y * b.y + a.z * b.z + a.w * b.w;
    v += __shfl_down_sync(0xffffffffu, v, 8);
    v += __shfl_down_sync(0xffffffffu, v, 4);
    v += __shfl_down_sync(0xffffffffu, v, 2);
    v += __shfl_down_sync(0xffffffffu, v, 1);
    if ((gt & 15) == 0) out[e] = v;
}

// ---------------- launcher ---------------------------------------------------

extern "C" void kernel_launch(void* const* d_in, const int* in_sizes, int n_in,
                              void* d_out, int out_size) {
    const float* user_emb = (const float*)d_in[0];
    const float* item_x   = (const float*)d_in[1];
    const float* item_w   = (const float*)d_in[2];
    const float* item_b   = (const float*)d_in[3];
    const float* Wl1_ui = (const float*)d_in[4],  *Wr1_ui = (const float*)d_in[5],  *b1_ui = (const float*)d_in[6];
    const float* Wl1_iu = (const float*)d_in[7],  *Wr1_iu = (const float*)d_in[8],  *b1_iu = (const float*)d_in[9];
    const float* Wl2_ui = (const float*)d_in[10], *Wr2_ui = (const float*)d_in[11], *b2_ui = (const float*)d_in[12];
    const float* Wl2_iu = (const float*)d_in[13], *Wr2_iu = (const float*)d_in[14], *b2_iu = (const float*)d_in[15];
    // d_in[16] = user_node_id (arange -> identity gather)
    const int* esrc = (const int*)d_in[17];
    const int* edst = (const int*)d_in[18];
    const int* lsrc = (const int*)d_in[19];
    const int* ldst = (const int*)d_in[20];
    float* out = (float*)d_out;

    float *p_xitem, *p_accu, *p_acci, *p_hu, *p_hi, *p_hu2, *p_hi2;
    int *p_degu, *p_degi, *p_offu, *p_offi, *p_curu, *p_curi, *p_bsu, *p_bsi, *p_nbru, *p_nbri;
    cudaGetSymbolAddress((void**)&p_xitem, g_xitem);
    cudaGetSymbolAddress((void**)&p_accu,  g_acc_u);
    cudaGetSymbolAddress((void**)&p_acci,  g_acc_i);
    cudaGetSymbolAddress((void**)&p_hu,    g_hu);
    cudaGetSymbolAddress((void**)&p_hi,    g_hi);
    cudaGetSymbolAddress((void**)&p_hu2,   g_hu2);
    cudaGetSymbolAddress((void**)&p_hi2,   g_hi2);
    cudaGetSymbolAddress((void**)&p_degu,  g_degu);
    cudaGetSymbolAddress((void**)&p_degi,  g_degi);
    cudaGetSymbolAddress((void**)&p_offu,  g_offu);
    cudaGetSymbolAddress((void**)&p_offi,  g_offi);
    cudaGetSymbolAddress((void**)&p_curu,  g_curu);
    cudaGetSymbolAddress((void**)&p_curi,  g_curi);
    cudaGetSymbolAddress((void**)&p_bsu,   g_bsu);
    cudaGetSymbolAddress((void**)&p_bsi,   g_bsi);
    cudaGetSymbolAddress((void**)&p_nbru,  g_nbru);
    cudaGetSymbolAddress((void**)&p_nbri,  g_nbri);

    // ---- CSR build (once; reused by both layers) ----
    zero_kernel<<<512, 256>>>((float4*)p_degu, (size_t)NU / 4);
    zero_kernel<<<128, 256>>>((float4*)p_degi, (size_t)NI / 4);
    count_kernel<<<(NE + 255) / 256, 256>>>(esrc, edst, p_degu, p_degi);

    int nbu = (NU + 1023) / 1024;   // 489
    int nbi = (NI + 1023) / 1024;   // 98
    scan_block_k<<<nbu, 1024>>>(p_degu, p_offu, p_bsu, NU);
    scan_block_k<<<nbi, 1024>>>(p_degi, p_offi, p_bsi, NI);
    scan_sums_k<<<1, 512>>>(p_bsu, nbu);
    scan_sums_k<<<1, 512>>>(p_bsi, nbi);
    add_off_k<<<(NU + 1024) / 1024, 1024>>>(p_offu, p_bsu, NU, NE);
    add_off_k<<<(NI + 1024) / 1024, 1024>>>(p_offi, p_bsi, NI, NE);
    copy_int_k<<<(NU + 255) / 256, 256>>>(p_offu, p_curu, NU);
    copy_int_k<<<(NI + 255) / 256, 256>>>(p_offi, p_curi, NI);
    build_csr_k<<<(NE + 255) / 256, 256>>>(esrc, edst, p_curu, p_curi, p_nbru, p_nbri);

    // ---- item input projection ----
    item_linear2<<<(NI + 63) / 64, 256>>>(item_x, item_w, item_b, p_xitem);

    // ---- layer 1 ----
    agg_csr_k<<<((size_t)NI * 16 + 255) / 256, 256>>>(user_emb, p_offi, p_nbri, p_acci, NI);
    agg_csr_k<<<((size_t)NU * 16 + 255) / 256, 256>>>(p_xitem,  p_offu, p_nbru, p_accu, NU);
    node_update2<true><<<(NU + 63) / 64, 256>>>(p_accu, p_offu, user_emb,
                                                Wl1_iu, Wr1_iu, b1_iu, p_hu, NU);
    node_update2<true><<<(NI + 63) / 64, 256>>>(p_acci, p_offi, p_xitem,
                                                Wl1_ui, Wr1_ui, b1_ui, p_hi, NI);

    // ---- layer 2 ----
    agg_csr_k<<<((size_t)NI * 16 + 255) / 256, 256>>>(p_hu, p_offi, p_nbri, p_acci, NI);
    agg_csr_k<<<((size_t)NU * 16 + 255) / 256, 256>>>(p_hi, p_offu, p_nbru, p_accu, NU);
    node_update2<false><<<(NU + 63) / 64, 256>>>(p_accu, p_offu, p_hu,
                                                 Wl2_iu, Wr2_iu, b2_iu, p_hu2, NU);
    node_update2<false><<<(NI + 63) / 64, 256>>>(p_acci, p_offi, p_hi,
                                                 Wl2_ui, Wr2_ui, b2_ui, p_hi2, NI);

    // ---- predictor ----
    dot_kernel16<<<((size_t)EL * 16 + 255) / 256, 256>>>(p_hu2, p_hi2, lsrc, ldst, out);
}

// round 12
// speedup vs baseline: 2.8448x; 1.2009x over previous
#include <cuda_runtime.h>
#include <cuda_fp16.h>
#include <cstdint>

#define NU 500000
#define NI 100000
#define FDIM 300
#define D 64
#define NE 2000000
#define EL 1000000

using u64 = unsigned long long;

__device__ __forceinline__ u64 pack2(float lo, float hi) {
    u64 r; asm("mov.b64 %0, {%1, %2};" : "=l"(r) : "f"(lo), "f"(hi)); return r;
}
__device__ __forceinline__ void fma2(u64& acc, u64 a, u64 b) {
    asm("fma.rn.f32x2 %0, %1, %2, %0;" : "+l"(acc) : "l"(a), "l"(b));
}
__device__ __forceinline__ float2 unpack2(u64 v) {
    float2 f; asm("mov.b64 {%0, %1}, %2;" : "=f"(f.x), "=f"(f.y) : "l"(v)); return f;
}

union H8 { int4 i4; __half2 h2[4]; };
union H4 { uint2 u2; __half2 h2[2]; };

// ---------------- scratch (static device globals; allocation-free) ----------
__device__ __half g_xitem[(size_t)NI * D];
__device__ __half g_acc_u[(size_t)NU * D];
__device__ __half g_acc_i[(size_t)NI * D];
__device__ __half g_hu [(size_t)NU * D];
__device__ __half g_hi [(size_t)NI * D];
__device__ __half g_hu2[(size_t)NU * D];
__device__ __half g_hi2[(size_t)NI * D];

__device__ int g_degu[NU];
__device__ int g_degi[NI];
__device__ int g_offu[NU + 1];
__device__ int g_offi[NI + 1];
__device__ int g_curu[NU];
__device__ int g_curi[NI];
__device__ int g_bsu[512];
__device__ int g_bsi[512];
__device__ int g_nbru[NE];   // CSR by user: item neighbors
__device__ int g_nbri[NE];   // CSR by item: user neighbors

// ---------------- utility kernels -------------------------------------------

__global__ void zero_kernel(float4* __restrict__ p, size_t n4) {
    size_t i = (size_t)blockIdx.x * blockDim.x + threadIdx.x;
    size_t stride = (size_t)gridDim.x * blockDim.x;
    float4 z = make_float4(0.f, 0.f, 0.f, 0.f);
    for (; i < n4; i += stride) p[i] = z;
}

__global__ void count_kernel(const int* __restrict__ src, const int* __restrict__ dst,
                             int* __restrict__ du, int* __restrict__ di) {
    int e = blockIdx.x * blockDim.x + threadIdx.x;
    if (e >= NE) return;
    atomicAdd(&du[src[e]], 1);
    atomicAdd(&di[dst[e]], 1);
}

__global__ void scan_block_k(const int* __restrict__ in, int* __restrict__ out,
                             int* __restrict__ bsum, int n) {
    __shared__ int sh[1024];
    int tid = threadIdx.x;
    int i = blockIdx.x * 1024 + tid;
    int v = (i < n) ? in[i] : 0;
    sh[tid] = v;
    __syncthreads();
    for (int off = 1; off < 1024; off <<= 1) {
        int t = (tid >= off) ? sh[tid - off] : 0;
        __syncthreads();
        sh[tid] += t;
        __syncthreads();
    }
    if (i < n) out[i] = sh[tid] - v;      // exclusive
    if (tid == 1023) bsum[blockIdx.x] = sh[1023];
}

__global__ void scan_sums_k(int* __restrict__ bsum, int nb) {
    __shared__ int sh[512];
    int tid = threadIdx.x;
    int v = (tid < nb) ? bsum[tid] : 0;
    sh[tid] = v;
    __syncthreads();
    for (int off = 1; off < 512; off <<= 1) {
        int t = (tid >= off) ? sh[tid - off] : 0;
        __syncthreads();
        sh[tid] += t;
        __syncthreads();
    }
    if (tid < nb) bsum[tid] = sh[tid] - v;
}

// adds block prefix, also initializes cursor array
__global__ void add_off_k(int* __restrict__ offs, int* __restrict__ cur,
                          const int* __restrict__ bsum, int n, int total) {
    int i = blockIdx.x * 1024 + threadIdx.x;
    if (i < n) {
        int v = offs[i] + bsum[i >> 10];
        offs[i] = v;
        cur[i] = v;
    } else if (i == n) {
        offs[n] = total;
    }
}

__global__ void build_csr_k(const int* __restrict__ src, const int* __restrict__ dst,
                            int* __restrict__ curu, int* __restrict__ curi,
                            int* __restrict__ nbru, int* __restrict__ nbri) {
    int e = blockIdx.x * blockDim.x + threadIdx.x;
    if (e >= NE) return;
    int s = src[e], d = dst[e];
    nbru[atomicAdd(&curu[s], 1)] = d;
    nbri[atomicAdd(&curi[d], 1)] = s;
}

// ---------------- item input linear (register-tiled f32x2, fp16 out) --------
__global__ __launch_bounds__(256) void item_linear2(
    const float* __restrict__ A, const float* __restrict__ B,
    const float* __restrict__ bias, __half* __restrict__ C)
{
    __shared__ float sA[60 * 68];   // [k][row] transposed, padded stride 68
    __shared__ float sB[60 * 64];   // [k][col]
    int tid = threadIdx.x;
    int row0 = blockIdx.x * 64;
    int ni4 = (tid >> 4) << 2;
    int cj4 = (tid & 15) << 2;

    u64 acc2[2][4];
#pragma unroll
    for (int ip = 0; ip < 2; ip++)
#pragma unroll
        for (int j = 0; j < 4; j++) acc2[ip][j] = 0ull;

    for (int kt = 0; kt < FDIM; kt += 60) {
        __syncthreads();
        for (int idx = tid; idx < 64 * 60; idx += 256) {
            int r = idx / 60;
            int k = idx - r * 60;
            int row = row0 + r;
            sA[k * 68 + r] = (row < NI) ? A[(size_t)row * FDIM + kt + k] : 0.f;
        }
        for (int idx = tid; idx < 60 * 64; idx += 256) {
            int k = idx >> 6, c = idx & 63;
            sB[idx] = B[(kt + k) * 64 + c];
        }
        __syncthreads();
#pragma unroll 12
        for (int k = 0; k < 60; k++) {
            float4 f = *(const float4*)&sA[k * 68 + ni4];
            float4 w = *(const float4*)&sB[k * 64 + cj4];
            u64 f01 = pack2(f.x, f.y);
            u64 f23 = pack2(f.z, f.w);
            u64 w0 = pack2(w.x, w.x), w1 = pack2(w.y, w.y);
            u64 w2 = pack2(w.z, w.z), w3 = pack2(w.w, w.w);
            fma2(acc2[0][0], f01, w0); fma2(acc2[0][1], f01, w1);
            fma2(acc2[0][2], f01, w2); fma2(acc2[0][3], f01, w3);
            fma2(acc2[1][0], f23, w0); fma2(acc2[1][1], f23, w1);
            fma2(acc2[1][2], f23, w2); fma2(acc2[1][3], f23, w3);
        }
    }

    float res[4][4];
#pragma unroll
    for (int ip = 0; ip < 2; ip++)
#pragma unroll
        for (int j = 0; j < 4; j++) {
            float2 t = unpack2(acc2[ip][j]);
            res[2 * ip][j] = t.x;
            res[2 * ip + 1][j] = t.y;
        }
    float4 bv = *(const float4*)&bias[cj4];
#pragma unroll
    for (int i = 0; i < 4; i++) {
        int row = row0 + ni4 + i;
        if (row < NI) {
            H4 cv;
            cv.h2[0] = __floats2half2_rn(res[i][0] + bv.x, res[i][1] + bv.y);
            cv.h2[1] = __floats2half2_rn(res[i][2] + bv.z, res[i][3] + bv.w);
            *(uint2*)&C[(size_t)row * 64 + cj4] = cv.u2;
        }
    }
}

// ---------------- CSR aggregation ---------------------------------------------
// fp32 source -> fp16 sum; 16 lanes/node, float4 per lane
__global__ void agg_csr_f(const float* __restrict__ xs, const int* __restrict__ offs,
                          const int* __restrict__ nbr, __half* __restrict__ osum, int n) {
    int gt = blockIdx.x * blockDim.x + threadIdx.x;
    int node = gt >> 4;
    int l = (gt & 15) << 2;
    if (node >= n) return;
    int e = offs[node], end = offs[node + 1];
    float4 a = make_float4(0.f, 0.f, 0.f, 0.f);
    for (; e + 2 <= end; e += 2) {
        int s0 = __ldg(&nbr[e]);
        int s1 = __ldg(&nbr[e + 1]);
        float4 v0 = *(const float4*)&xs[(size_t)s0 * 64 + l];
        float4 v1 = *(const float4*)&xs[(size_t)s1 * 64 + l];
        a.x += v0.x + v1.x; a.y += v0.y + v1.y;
        a.z += v0.z + v1.z; a.w += v0.w + v1.w;
    }
    if (e < end) {
        int s0 = __ldg(&nbr[e]);
        float4 v0 = *(const float4*)&xs[(size_t)s0 * 64 + l];
        a.x += v0.x; a.y += v0.y; a.z += v0.z; a.w += v0.w;
    }
    H4 cv;
    cv.h2[0] = __floats2half2_rn(a.x, a.y);
    cv.h2[1] = __floats2half2_rn(a.z, a.w);
    *(uint2*)&osum[(size_t)node * 64 + l] = cv.u2;
}

// fp16 source -> fp16 sum; 8 lanes/node, 8 halves (int4) per lane
__global__ void agg_csr_h(const __half* __restrict__ xs, const int* __restrict__ offs,
                          const int* __restrict__ nbr, __half* __restrict__ osum, int n) {
    int gt = blockIdx.x * blockDim.x + threadIdx.x;
    int node = gt >> 3;
    int l = (gt & 7) << 3;
    if (node >= n) return;
    int e = offs[node], end = offs[node + 1];
    float a[8];
#pragma unroll
    for (int t = 0; t < 8; t++) a[t] = 0.f;
    for (; e + 2 <= end; e += 2) {
        int s0 = __ldg(&nbr[e]);
        int s1 = __ldg(&nbr[e + 1]);
        H8 v0, v1;
        v0.i4 = *(const int4*)&xs[(size_t)s0 * 64 + l];
        v1.i4 = *(const int4*)&xs[(size_t)s1 * 64 + l];
#pragma unroll
        for (int t = 0; t < 4; t++) {
            float2 f0 = __half22float2(v0.h2[t]);
            float2 f1 = __half22float2(v1.h2[t]);
            a[2 * t]     += f0.x + f1.x;
            a[2 * t + 1] += f0.y + f1.y;
        }
    }
    if (e < end) {
        int s0 = __ldg(&nbr[e]);
        H8 v0; v0.i4 = *(const int4*)&xs[(size_t)s0 * 64 + l];
#pragma unroll
        for (int t = 0; t < 4; t++) {
            float2 f0 = __half22float2(v0.h2[t]);
            a[2 * t]     += f0.x;
            a[2 * t + 1] += f0.y;
        }
    }
    H8 st;
#pragma unroll
    for (int t = 0; t < 4; t++) st.h2[t] = __floats2half2_rn(a[2 * t], a[2 * t + 1]);
    *(int4*)&osum[(size_t)node * 64 + l] = st.i4;
}

// ---------------- node update: register-tiled f32x2 GEMM, fp16 I/O ----------
// out[n][c] = (accsum[n]/deg) @ Wl + b + x[n] @ Wr   (optional ReLU)
template <bool RELU, bool XFLOAT>
__global__ __launch_bounds__(256) void node_update3(
    const __half* __restrict__ accsum, const int* __restrict__ offs,
    const void* __restrict__ xv,
    const float* __restrict__ Wl, const float* __restrict__ Wr,
    const float* __restrict__ bias, __half* __restrict__ out, int n)
{
    __shared__ float sW[64][64];      // weights [k][col]
    __shared__ float sF[64][64];      // features transposed [k][node]
    int tid = threadIdx.x;
    int base = blockIdx.x * 64;
    int nl = tid & 63;
    int node = base + nl;
    bool valid = node < n;
    float invd = 1.0f;
    if (valid) {
        int beg = offs[node], end = offs[node + 1];
        invd = 1.0f / fmaxf((float)(end - beg), 1.0f);
    }
    int ni4 = (tid >> 4) << 2;
    int cj4 = (tid & 15) << 2;

    u64 acc2[2][4];
#pragma unroll
    for (int ip = 0; ip < 2; ip++)
#pragma unroll
        for (int j = 0; j < 4; j++) acc2[ip][j] = 0ull;

#pragma unroll
    for (int pass = 0; pass < 2; pass++) {
        __syncthreads();
        const float4* wsrc = (const float4*)(pass == 0 ? Wl : Wr);
        float4* wdst = (float4*)&sW[0][0];
        for (int i = tid; i < 1024; i += 256) wdst[i] = wsrc[i];

        if (XFLOAT && pass == 1) {
            const float* fsrc = (const float*)xv;
            for (int kq = tid >> 6; kq < 16; kq += 4) {
                float4 v = valid ? *(const float4*)&fsrc[(size_t)node * 64 + kq * 4]
                                 : make_float4(0.f, 0.f, 0.f, 0.f);
                sF[kq * 4 + 0][nl] = v.x;
                sF[kq * 4 + 1][nl] = v.y;
                sF[kq * 4 + 2][nl] = v.z;
                sF[kq * 4 + 3][nl] = v.w;
            }
        } else {
            const __half* fsrc = (pass == 0) ? accsum : (const __half*)xv;
            float scale = (pass == 0) ? invd : 1.0f;
            for (int kq = tid >> 6; kq < 8; kq += 4) {
                H8 raw;
                if (valid) raw.i4 = *(const int4*)&fsrc[(size_t)node * 64 + kq * 8];
                else raw.i4 = make_int4(0, 0, 0, 0);
#pragma unroll
                for (int t = 0; t < 4; t++) {
                    float2 f = __half22float2(raw.h2[t]);
                    sF[kq * 8 + 2 * t + 0][nl] = f.x * scale;
                    sF[kq * 8 + 2 * t + 1][nl] = f.y * scale;
                }
            }
        }
        __syncthreads();
#pragma unroll 16
        for (int k = 0; k < 64; k++) {
            float4 f = *(const float4*)&sF[k][ni4];
            float4 w = *(const float4*)&sW[k][cj4];
            u64 f01 = pack2(f.x, f.y);
            u64 f23 = pack2(f.z, f.w);
            u64 w0 = pack2(w.x, w.x), w1 = pack2(w.y, w.y);
            u64 w2 = pack2(w.z, w.z), w3 = pack2(w.w, w.w);
            fma2(acc2[0][0], f01, w0); fma2(acc2[0][1], f01, w1);
            fma2(acc2[0][2], f01, w2); fma2(acc2[0][3], f01, w3);
            fma2(acc2[1][0], f23, w0); fma2(acc2[1][1], f23, w1);
            fma2(acc2[1][2], f23, w2); fma2(acc2[1][3], f23, w3);
        }
    }

    float res[4][4];
#pragma unroll
    for (int ip = 0; ip < 2; ip++)
#pragma unroll
        for (int j = 0; j < 4; j++) {
            float2 t = unpack2(acc2[ip][j]);
            res[2 * ip][j] = t.x;
            res[2 * ip + 1][j] = t.y;
        }
    float4 bv = *(const float4*)&bias[cj4];
#pragma unroll
    for (int i = 0; i < 4; i++) {
        int nd = base + ni4 + i;
        if (nd < n) {
            float o0 = res[i][0] + bv.x;
            float o1 = res[i][1] + bv.y;
            float o2 = res[i][2] + bv.z;
            float o3 = res[i][3] + bv.w;
            if (RELU) {
                o0 = fmaxf(o0, 0.f); o1 = fmaxf(o1, 0.f);
                o2 = fmaxf(o2, 0.f); o3 = fmaxf(o3, 0.f);
            }
            H4 cv;
            cv.h2[0] = __floats2half2_rn(o0, o1);
            cv.h2[1] = __floats2half2_rn(o2, o3);
            *(uint2*)&out[(size_t)nd * 64 + cj4] = cv.u2;
        }
    }
}

// ---------------- dot predictor: 8 lanes per edge, fp16 rows -----------------
__global__ void dot_kernel8(const __half* __restrict__ hu, const __half* __restrict__ hi,
                            const int* __restrict__ ls, const int* __restrict__ ld,
                            float* __restrict__ out) {
    int gt = blockIdx.x * blockDim.x + threadIdx.x;
    int e = gt >> 3;
    int l = (gt & 7) << 3;
    if (e >= EL) return;
    int s = __ldg(&ls[e]);
    int d = __ldg(&ld[e]);
    H8 a, b;
    a.i4 = *(const int4*)&hu[(size_t)s * 64 + l];
    b.i4 = *(const int4*)&hi[(size_t)d * 64 + l];
    float v = 0.f;
#pragma unroll
    for (int t = 0; t < 4; t++) {
        float2 fa = __half22float2(a.h2[t]);
        float2 fb = __half22float2(b.h2[t]);
        v += fa.x * fb.x + fa.y * fb.y;
    }
    v += __shfl_down_sync(0xffffffffu, v, 4);
    v += __shfl_down_sync(0xffffffffu, v, 2);
    v += __shfl_down_sync(0xffffffffu, v, 1);
    if ((gt & 7) == 0) out[e] = v;
}

// ---------------- launcher ---------------------------------------------------

extern "C" void kernel_launch(void* const* d_in, const int* in_sizes, int n_in,
                              void* d_out, int out_size) {
    const float* user_emb = (const float*)d_in[0];
    const float* item_x   = (const float*)d_in[1];
    const float* item_w   = (const float*)d_in[2];
    const float* item_b   = (const float*)d_in[3];
    const float* Wl1_ui = (const float*)d_in[4],  *Wr1_ui = (const float*)d_in[5],  *b1_ui = (const float*)d_in[6];
    const float* Wl1_iu = (const float*)d_in[7],  *Wr1_iu = (const float*)d_in[8],  *b1_iu = (const float*)d_in[9];
    const float* Wl2_ui = (const float*)d_in[10], *Wr2_ui = (const float*)d_in[11], *b2_ui = (const float*)d_in[12];
    const float* Wl2_iu = (const float*)d_in[13], *Wr2_iu = (const float*)d_in[14], *b2_iu = (const float*)d_in[15];
    // d_in[16] = user_node_id (arange -> identity gather)
    const int* esrc = (const int*)d_in[17];
    const int* edst = (const int*)d_in[18];
    const int* lsrc = (const int*)d_in[19];
    const int* ldst = (const int*)d_in[20];
    float* out = (float*)d_out;

    __half *p_xitem, *p_accu, *p_acci, *p_hu, *p_hi, *p_hu2, *p_hi2;
    int *p_degu, *p_degi, *p_offu, *p_offi, *p_curu, *p_curi, *p_bsu, *p_bsi, *p_nbru, *p_nbri;
    cudaGetSymbolAddress((void**)&p_xitem, g_xitem);
    cudaGetSymbolAddress((void**)&p_accu,  g_acc_u);
    cudaGetSymbolAddress((void**)&p_acci,  g_acc_i);
    cudaGetSymbolAddress((void**)&p_hu,    g_hu);
    cudaGetSymbolAddress((void**)&p_hi,    g_hi);
    cudaGetSymbolAddress((void**)&p_hu2,   g_hu2);
    cudaGetSymbolAddress((void**)&p_hi2,   g_hi2);
    cudaGetSymbolAddress((void**)&p_degu,  g_degu);
    cudaGetSymbolAddress((void**)&p_degi,  g_degi);
    cudaGetSymbolAddress((void**)&p_offu,  g_offu);
    cudaGetSymbolAddress((void**)&p_offi,  g_offi);
    cudaGetSymbolAddress((void**)&p_curu,  g_curu);
    cudaGetSymbolAddress((void**)&p_curi,  g_curi);
    cudaGetSymbolAddress((void**)&p_bsu,   g_bsu);
    cudaGetSymbolAddress((void**)&p_bsi,   g_bsi);
    cudaGetSymbolAddress((void**)&p_nbru,  g_nbru);
    cudaGetSymbolAddress((void**)&p_nbri,  g_nbri);

    // ---- CSR build (once; reused by both layers) ----
    zero_kernel<<<512, 256>>>((float4*)p_degu, (size_t)NU / 4);
    zero_kernel<<<128, 256>>>((float4*)p_degi, (size_t)NI / 4);
    count_kernel<<<(NE + 255) / 256, 256>>>(esrc, edst, p_degu, p_degi);

    int nbu = (NU + 1023) / 1024;   // 489
    int nbi = (NI + 1023) / 1024;   // 98
    scan_block_k<<<nbu, 1024>>>(p_degu, p_offu, p_bsu, NU);
    scan_block_k<<<nbi, 1024>>>(p_degi, p_offi, p_bsi, NI);
    scan_sums_k<<<1, 512>>>(p_bsu, nbu);
    scan_sums_k<<<1, 512>>>(p_bsi, nbi);
    add_off_k<<<(NU + 1024) / 1024, 1024>>>(p_offu, p_curu, p_bsu, NU, NE);
    add_off_k<<<(NI + 1024) / 1024, 1024>>>(p_offi, p_curi, p_bsi, NI, NE);
    build_csr_k<<<(NE + 255) / 256, 256>>>(esrc, edst, p_curu, p_curi, p_nbru, p_nbri);

    // ---- item input projection ----
    item_linear2<<<(NI + 63) / 64, 256>>>(item_x, item_w, item_b, p_xitem);

    // ---- layer 1 ----
    agg_csr_f<<<((size_t)NI * 16 + 255) / 256, 256>>>(user_emb, p_offi, p_nbri, p_acci, NI);
    agg_csr_h<<<((size_t)NU * 8 + 255) / 256, 256>>>(p_xitem,  p_offu, p_nbru, p_accu, NU);
    node_update3<true, true><<<(NU + 63) / 64, 256>>>(p_accu, p_offu, user_emb,
                                                      Wl1_iu, Wr1_iu, b1_iu, p_hu, NU);
    node_update3<true, false><<<(NI + 63) / 64, 256>>>(p_acci, p_offi, p_xitem,
                                                       Wl1_ui, Wr1_ui, b1_ui, p_hi, NI);

    // ---- layer 2 ----
    agg_csr_h<<<((size_t)NI * 8 + 255) / 256, 256>>>(p_hu, p_offi, p_nbri, p_acci, NI);
    agg_csr_h<<<((size_t)NU * 8 + 255) / 256, 256>>>(p_hi, p_offu, p_nbru, p_accu, NU);
    node_update3<false, false><<<(NU + 63) / 64, 256>>>(p_accu, p_offu, p_hu,
                                                        Wl2_iu, Wr2_iu, b2_iu, p_hu2, NU);
    node_update3<false, false><<<(NI + 63) / 64, 256>>>(p_acci, p_offi, p_hi,
                                                        Wl2_ui, Wr2_ui, b2_ui, p_hi2, NI);

    // ---- predictor ----
    dot_kernel8<<<((size_t)EL * 8 + 255) / 256, 256>>>(p_hu2, p_hi2, lsrc, ldst, out);
}

// round 13
// speedup vs baseline: 4.2721x; 1.5017x over previous
#include <cuda_runtime.h>
#include <cuda_fp16.h>
#include <cstdint>

#define NU 500000
#define NI 100000
#define FDIM 300
#define D 64
#define NE 2000000
#define EL 1000000

using u64 = unsigned long long;

__device__ __forceinline__ u64 pack2(float lo, float hi) {
    u64 r; asm("mov.b64 %0, {%1, %2};" : "=l"(r) : "f"(lo), "f"(hi)); return r;
}
__device__ __forceinline__ void fma2(u64& acc, u64 a, u64 b) {
    asm("fma.rn.f32x2 %0, %1, %2, %0;" : "+l"(acc) : "l"(a), "l"(b));
}
__device__ __forceinline__ float2 unpack2(u64 v) {
    float2 f; asm("mov.b64 {%0, %1}, %2;" : "=f"(f.x), "=f"(f.y) : "l"(v)); return f;
}

union H8 { int4 i4; __half2 h2[4]; };
union H4 { uint2 u2; __half2 h2[2]; };

__device__ __forceinline__ uint32_t smem_u32(const void* p) {
    return (uint32_t)__cvta_generic_to_shared(p);
}
__device__ __forceinline__ void ldsm_x4(uint32_t& r0, uint32_t& r1, uint32_t& r2, uint32_t& r3,
                                        uint32_t addr) {
    asm volatile("ldmatrix.sync.aligned.m8n8.x4.shared.b16 {%0,%1,%2,%3}, [%4];"
                 : "=r"(r0), "=r"(r1), "=r"(r2), "=r"(r3) : "r"(addr));
}
__device__ __forceinline__ void ldsm_x4t(uint32_t& r0, uint32_t& r1, uint32_t& r2, uint32_t& r3,
                                         uint32_t addr) {
    asm volatile("ldmatrix.sync.aligned.m8n8.x4.trans.shared.b16 {%0,%1,%2,%3}, [%4];"
                 : "=r"(r0), "=r"(r1), "=r"(r2), "=r"(r3) : "r"(addr));
}
__device__ __forceinline__ void mma16816(float* c, uint32_t a0, uint32_t a1, uint32_t a2,
                                         uint32_t a3, uint32_t b0, uint32_t b1) {
    asm volatile(
        "mma.sync.aligned.m16n8k16.row.col.f32.f16.f16.f32 "
        "{%0,%1,%2,%3}, {%4,%5,%6,%7}, {%8,%9}, {%0,%1,%2,%3};"
        : "+f"(c[0]), "+f"(c[1]), "+f"(c[2]), "+f"(c[3])
        : "r"(a0), "r"(a1), "r"(a2), "r"(a3), "r"(b0), "r"(b1));
}

// ---------------- scratch (static device globals; allocation-free) ----------
__device__ __half g_uemb16[(size_t)NU * D];
__device__ __half g_xitem[(size_t)NI * D];
__device__ __half g_acc_u[(size_t)NU * D];
__device__ __half g_acc_i[(size_t)NI * D];
__device__ __half g_hu [(size_t)NU * D];
__device__ __half g_hi [(size_t)NI * D];
__device__ __half g_hu2[(size_t)NU * D];
__device__ __half g_hi2[(size_t)NI * D];

__device__ int g_degu[NU];
__device__ int g_degi[NI];
__device__ int g_offu[NU + 1];
__device__ int g_offi[NI + 1];
__device__ int g_curu[NU];
__device__ int g_curi[NI];
__device__ int g_bsu[512];
__device__ int g_bsi[512];
__device__ int g_nbru[NE];   // CSR by user: item neighbors
__device__ int g_nbri[NE];   // CSR by item: user neighbors

// ---------------- utility kernels -------------------------------------------

__global__ void zero_kernel(float4* __restrict__ p, size_t n4) {
    size_t i = (size_t)blockIdx.x * blockDim.x + threadIdx.x;
    size_t stride = (size_t)gridDim.x * blockDim.x;
    float4 z = make_float4(0.f, 0.f, 0.f, 0.f);
    for (; i < n4; i += stride) p[i] = z;
}

__global__ void cast_f2h(const float4* __restrict__ src, uint2* __restrict__ dst, size_t n4) {
    size_t i = (size_t)blockIdx.x * blockDim.x + threadIdx.x;
    size_t stride = (size_t)gridDim.x * blockDim.x;
    for (; i < n4; i += stride) {
        float4 v = src[i];
        H4 cv;
        cv.h2[0] = __floats2half2_rn(v.x, v.y);
        cv.h2[1] = __floats2half2_rn(v.z, v.w);
        dst[i] = cv.u2;
    }
}

__global__ void count_kernel(const int* __restrict__ src, const int* __restrict__ dst,
                             int* __restrict__ du, int* __restrict__ di) {
    int e = blockIdx.x * blockDim.x + threadIdx.x;
    if (e >= NE) return;
    atomicAdd(&du[src[e]], 1);
    atomicAdd(&di[dst[e]], 1);
}

__global__ void scan_block_k(const int* __restrict__ in, int* __restrict__ out,
                             int* __restrict__ bsum, int n) {
    __shared__ int sh[1024];
    int tid = threadIdx.x;
    int i = blockIdx.x * 1024 + tid;
    int v = (i < n) ? in[i] : 0;
    sh[tid] = v;
    __syncthreads();
    for (int off = 1; off < 1024; off <<= 1) {
        int t = (tid >= off) ? sh[tid - off] : 0;
        __syncthreads();
        sh[tid] += t;
        __syncthreads();
    }
    if (i < n) out[i] = sh[tid] - v;      // exclusive
    if (tid == 1023) bsum[blockIdx.x] = sh[1023];
}

__global__ void scan_sums_k(int* __restrict__ bsum, int nb) {
    __shared__ int sh[512];
    int tid = threadIdx.x;
    int v = (tid < nb) ? bsum[tid] : 0;
    sh[tid] = v;
    __syncthreads();
    for (int off = 1; off < 512; off <<= 1) {
        int t = (tid >= off) ? sh[tid - off] : 0;
        __syncthreads();
        sh[tid] += t;
        __syncthreads();
    }
    if (tid < nb) bsum[tid] = sh[tid] - v;
}

__global__ void add_off_k(int* __restrict__ offs, int* __restrict__ cur,
                          const int* __restrict__ bsum, int n, int total) {
    int i = blockIdx.x * 1024 + threadIdx.x;
    if (i < n) {
        int v = offs[i] + bsum[i >> 10];
        offs[i] = v;
        cur[i] = v;
    } else if (i == n) {
        offs[n] = total;
    }
}

__global__ void build_csr_k(const int* __restrict__ src, const int* __restrict__ dst,
                            int* __restrict__ curu, int* __restrict__ curi,
                            int* __restrict__ nbru, int* __restrict__ nbri) {
    int e = blockIdx.x * blockDim.x + threadIdx.x;
    if (e >= NE) return;
    int s = src[e], d = dst[e];
    nbru[atomicAdd(&curu[s], 1)] = d;
    nbri[atomicAdd(&curi[d], 1)] = s;
}

// ---------------- item input linear (register-tiled f32x2, fp16 out) --------
__global__ __launch_bounds__(256) void item_linear2(
    const float* __restrict__ A, const float* __restrict__ B,
    const float* __restrict__ bias, __half* __restrict__ C)
{
    __shared__ float sA[60 * 68];   // [k][row] transposed, padded stride 68
    __shared__ float sB[60 * 64];   // [k][col]
    int tid = threadIdx.x;
    int row0 = blockIdx.x * 64;
    int ni4 = (tid >> 4) << 2;
    int cj4 = (tid & 15) << 2;

    u64 acc2[2][4];
#pragma unroll
    for (int ip = 0; ip < 2; ip++)
#pragma unroll
        for (int j = 0; j < 4; j++) acc2[ip][j] = 0ull;

    for (int kt = 0; kt < FDIM; kt += 60) {
        __syncthreads();
        for (int idx = tid; idx < 64 * 60; idx += 256) {
            int r = idx / 60;
            int k = idx - r * 60;
            int row = row0 + r;
            sA[k * 68 + r] = (row < NI) ? A[(size_t)row * FDIM + kt + k] : 0.f;
        }
        for (int idx = tid; idx < 60 * 64; idx += 256) {
            int k = idx >> 6, c = idx & 63;
            sB[idx] = B[(kt + k) * 64 + c];
        }
        __syncthreads();
#pragma unroll 12
        for (int k = 0; k < 60; k++) {
            float4 f = *(const float4*)&sA[k * 68 + ni4];
            float4 w = *(const float4*)&sB[k * 64 + cj4];
            u64 f01 = pack2(f.x, f.y);
            u64 f23 = pack2(f.z, f.w);
            u64 w0 = pack2(w.x, w.x), w1 = pack2(w.y, w.y);
            u64 w2 = pack2(w.z, w.z), w3 = pack2(w.w, w.w);
            fma2(acc2[0][0], f01, w0); fma2(acc2[0][1], f01, w1);
            fma2(acc2[0][2], f01, w2); fma2(acc2[0][3], f01, w3);
            fma2(acc2[1][0], f23, w0); fma2(acc2[1][1], f23, w1);
            fma2(acc2[1][2], f23, w2); fma2(acc2[1][3], f23, w3);
        }
    }

    float res[4][4];
#pragma unroll
    for (int ip = 0; ip < 2; ip++)
#pragma unroll
        for (int j = 0; j < 4; j++) {
            float2 t = unpack2(acc2[ip][j]);
            res[2 * ip][j] = t.x;
            res[2 * ip + 1][j] = t.y;
        }
    float4 bv = *(const float4*)&bias[cj4];
#pragma unroll
    for (int i = 0; i < 4; i++) {
        int row = row0 + ni4 + i;
        if (row < NI) {
            H4 cv;
            cv.h2[0] = __floats2half2_rn(res[i][0] + bv.x, res[i][1] + bv.y);
            cv.h2[1] = __floats2half2_rn(res[i][2] + bv.z, res[i][3] + bv.w);
            *(uint2*)&C[(size_t)row * 64 + cj4] = cv.u2;
        }
    }
}

// ---------------- CSR aggregation (fp16 src -> fp16 sum) --------------------
__global__ void agg_csr_h(const __half* __restrict__ xs, const int* __restrict__ offs,
                          const int* __restrict__ nbr, __half* __restrict__ osum, int n) {
    int gt = blockIdx.x * blockDim.x + threadIdx.x;
    int node = gt >> 3;
    int l = (gt & 7) << 3;
    if (node >= n) return;
    int e = offs[node], end = offs[node + 1];
    float a[8];
#pragma unroll
    for (int t = 0; t < 8; t++) a[t] = 0.f;
    for (; e + 2 <= end; e += 2) {
        int s0 = __ldg(&nbr[e]);
        int s1 = __ldg(&nbr[e + 1]);
        H8 v0, v1;
        v0.i4 = *(const int4*)&xs[(size_t)s0 * 64 + l];
        v1.i4 = *(const int4*)&xs[(size_t)s1 * 64 + l];
#pragma unroll
        for (int t = 0; t < 4; t++) {
            float2 f0 = __half22float2(v0.h2[t]);
            float2 f1 = __half22float2(v1.h2[t]);
            a[2 * t]     += f0.x + f1.x;
            a[2 * t + 1] += f0.y + f1.y;
        }
    }
    if (e < end) {
        int s0 = __ldg(&nbr[e]);
        H8 v0; v0.i4 = *(const int4*)&xs[(size_t)s0 * 64 + l];
#pragma unroll
        for (int t = 0; t < 4; t++) {
            float2 f0 = __half22float2(v0.h2[t]);
            a[2 * t]     += f0.x;
            a[2 * t + 1] += f0.y;
        }
    }
    H8 st;
#pragma unroll
    for (int t = 0; t < 4; t++) st.h2[t] = __floats2half2_rn(a[2 * t], a[2 * t + 1]);
    *(int4*)&osum[(size_t)node * 64 + l] = st.i4;
}

// ---------------- node update: HMMA (mma.sync m16n8k16) ---------------------
// out[n][c] = (accsum[n]/deg) @ Wl + b + x[n] @ Wr   (optional ReLU)
// Tile: 64 nodes (M) x 64 cols (N) x K=128 ([agg ; x] against [Wl ; Wr]).
// 8 warps: warp w -> m0=(w&3)*16, n0=(w>>2)*32.
template <bool RELU>
__global__ __launch_bounds__(256) void node_update_mma(
    const __half* __restrict__ accsum, const int* __restrict__ offs,
    const __half* __restrict__ x,
    const float* __restrict__ Wl, const float* __restrict__ Wr,
    const float* __restrict__ bias, __half* __restrict__ out, int n)
{
    __shared__ __half sA[64][136];   // [node][k], pad 8 halves (16B) per row
    __shared__ __half sB[128][72];   // [k][col],  pad 8 halves per row
    int tid = threadIdx.x;
    int base = blockIdx.x * 64;

    // ---- stage B: weights fp32 -> fp16, [Wl ; Wr] stacked on K ----
#pragma unroll
    for (int q = 0; q < 8; q++) {
        int idx = tid + q * 256;          // 2048 float4 total
        int k = idx >> 4;
        int c = (idx & 15) << 2;
        float4 w = (k < 64) ? *(const float4*)&Wl[k * 64 + c]
                            : *(const float4*)&Wr[(k - 64) * 64 + c];
        H4 cv;
        cv.h2[0] = __floats2half2_rn(w.x, w.y);
        cv.h2[1] = __floats2half2_rn(w.z, w.w);
        *(uint2*)&sB[k][c] = cv.u2;
    }
    // ---- stage A: features [agg/deg ; x] ----
#pragma unroll
    for (int q = 0; q < 4; q++) {
        int idx = tid + q * 256;          // 1024 int4 total (16 per node row)
        int nl = idx >> 4;
        int pos = (idx & 15) << 3;
        int node = base + nl;
        H8 v;
        if (node < n) {
            if (pos < 64) {
                v.i4 = *(const int4*)&accsum[(size_t)node * 64 + pos];
                int deg = offs[node + 1] - offs[node];
                float invd = 1.0f / fmaxf((float)deg, 1.0f);
#pragma unroll
                for (int t = 0; t < 4; t++) {
                    float2 f = __half22float2(v.h2[t]);
                    v.h2[t] = __floats2half2_rn(f.x * invd, f.y * invd);
                }
            } else {
                v.i4 = *(const int4*)&x[(size_t)node * 64 + (pos - 64)];
            }
        } else {
            v.i4 = make_int4(0, 0, 0, 0);
        }
        *(int4*)&sA[nl][pos] = v.i4;
    }
    __syncthreads();

    int warp = tid >> 5, lane = tid & 31;
    int m0 = (warp & 3) * 16;
    int n0 = (warp >> 2) * 32;

    float acc[4][4];
#pragma unroll
    for (int i = 0; i < 4; i++)
#pragma unroll
        for (int j = 0; j < 4; j++) acc[i][j] = 0.f;

    uint32_t aBase = smem_u32(&sA[m0 + (lane & 15)][(lane >> 4) * 8]);
    uint32_t bBase0 = smem_u32(&sB[lane & 15][n0 + (lane >> 4) * 8]);
    uint32_t bBase1 = smem_u32(&sB[lane & 15][n0 + 16 + (lane >> 4) * 8]);
    const uint32_t A_ROW = 136 * 2;   // bytes per sA row
    const uint32_t B_ROW = 72 * 2;    // bytes per sB row

#pragma unroll
    for (int ks = 0; ks < 8; ks++) {
        uint32_t a0, a1, a2, a3;
        ldsm_x4(a0, a1, a2, a3, aBase + ks * 32);           // +16 halves in k
        uint32_t b0, b1, b2, b3;
        ldsm_x4t(b0, b1, b2, b3, bBase0 + ks * 16 * B_ROW); // +16 rows in k
        mma16816(acc[0], a0, a1, a2, a3, b0, b1);
        mma16816(acc[1], a0, a1, a2, a3, b2, b3);
        ldsm_x4t(b0, b1, b2, b3, bBase1 + ks * 16 * B_ROW);
        mma16816(acc[2], a0, a1, a2, a3, b0, b1);
        mma16816(acc[3], a0, a1, a2, a3, b2, b3);
    }

    // ---- epilogue: bias + relu, stage fp16 in smem (reuse sA), coalesced out
    __syncthreads();
    __half (*sOut)[72] = (__half(*)[72])&sA[0][0];   // 64 x 72 halves = 9.2 KB
    int row = lane >> 2;
    int cb = (lane & 3) * 2;
#pragma unroll
    for (int nsub = 0; nsub < 4; nsub++) {
        int col = n0 + nsub * 8 + cb;
        float bv0 = bias[col], bv1 = bias[col + 1];
        float o0 = acc[nsub][0] + bv0;
        float o1 = acc[nsub][1] + bv1;
        float o2 = acc[nsub][2] + bv0;
        float o3 = acc[nsub][3] + bv1;
        if (RELU) {
            o0 = fmaxf(o0, 0.f); o1 = fmaxf(o1, 0.f);
            o2 = fmaxf(o2, 0.f); o3 = fmaxf(o3, 0.f);
        }
        *(__half2*)&sOut[m0 + row][col]     = __floats2half2_rn(o0, o1);
        *(__half2*)&sOut[m0 + row + 8][col] = __floats2half2_rn(o2, o3);
    }
    __syncthreads();
#pragma unroll
    for (int q = 0; q < 2; q++) {
        int idx = tid + q * 256;          // 512 int4 total
        int nl = idx >> 3;
        int c = (idx & 7) << 3;
        int node = base + nl;
        if (node < n)
            *(int4*)&out[(size_t)node * 64 + c] = *(const int4*)&sOut[nl][c];
    }
}

// ---------------- dot predictor: 8 lanes per edge, fp16 rows -----------------
__global__ void dot_kernel8(const __half* __restrict__ hu, const __half* __restrict__ hi,
                            const int* __restrict__ ls, const int* __restrict__ ld,
                            float* __restrict__ out) {
    int gt = blockIdx.x * blockDim.x + threadIdx.x;
    int e = gt >> 3;
    int l = (gt & 7) << 3;
    if (e >= EL) return;
    int s = __ldg(&ls[e]);
    int d = __ldg(&ld[e]);
    H8 a, b;
    a.i4 = *(const int4*)&hu[(size_t)s * 64 + l];
    b.i4 = *(const int4*)&hi[(size_t)d * 64 + l];
    float v = 0.f;
#pragma unroll
    for (int t = 0; t < 4; t++) {
        float2 fa = __half22float2(a.h2[t]);
        float2 fb = __half22float2(b.h2[t]);
        v += fa.x * fb.x + fa.y * fb.y;
    }
    v += __shfl_down_sync(0xffffffffu, v, 4);
    v += __shfl_down_sync(0xffffffffu, v, 2);
    v += __shfl_down_sync(0xffffffffu, v, 1);
    if ((gt & 7) == 0) out[e] = v;
}

// ---------------- launcher ---------------------------------------------------

extern "C" void kernel_launch(void* const* d_in, const int* in_sizes, int n_in,
                              void* d_out, int out_size) {
    const float* user_emb = (const float*)d_in[0];
    const float* item_x   = (const float*)d_in[1];
    const float* item_w   = (const float*)d_in[2];
    const float* item_b   = (const float*)d_in[3];
    const float* Wl1_ui = (const float*)d_in[4],  *Wr1_ui = (const float*)d_in[5],  *b1_ui = (const float*)d_in[6];
    const float* Wl1_iu = (const float*)d_in[7],  *Wr1_iu = (const float*)d_in[8],  *b1_iu = (const float*)d_in[9];
    const float* Wl2_ui = (const float*)d_in[10], *Wr2_ui = (const float*)d_in[11], *b2_ui = (const float*)d_in[12];
    const float* Wl2_iu = (const float*)d_in[13], *Wr2_iu = (const float*)d_in[14], *b2_iu = (const float*)d_in[15];
    // d_in[16] = user_node_id (arange -> identity gather)
    const int* esrc = (const int*)d_in[17];
    const int* edst = (const int*)d_in[18];
    const int* lsrc = (const int*)d_in[19];
    const int* ldst = (const int*)d_in[20];
    float* out = (float*)d_out;

    __half *p_uemb16, *p_xitem, *p_accu, *p_acci, *p_hu, *p_hi, *p_hu2, *p_hi2;
    int *p_degu, *p_degi, *p_offu, *p_offi, *p_curu, *p_curi, *p_bsu, *p_bsi, *p_nbru, *p_nbri;
    cudaGetSymbolAddress((void**)&p_uemb16, g_uemb16);
    cudaGetSymbolAddress((void**)&p_xitem, g_xitem);
    cudaGetSymbolAddress((void**)&p_accu,  g_acc_u);
    cudaGetSymbolAddress((void**)&p_acci,  g_acc_i);
    cudaGetSymbolAddress((void**)&p_hu,    g_hu);
    cudaGetSymbolAddress((void**)&p_hi,    g_hi);
    cudaGetSymbolAddress((void**)&p_hu2,   g_hu2);
    cudaGetSymbolAddress((void**)&p_hi2,   g_hi2);
    cudaGetSymbolAddress((void**)&p_degu,  g_degu);
    cudaGetSymbolAddress((void**)&p_degi,  g_degi);
    cudaGetSymbolAddress((void**)&p_offu,  g_offu);
    cudaGetSymbolAddress((void**)&p_offi,  g_offi);
    cudaGetSymbolAddress((void**)&p_curu,  g_curu);
    cudaGetSymbolAddress((void**)&p_curi,  g_curi);
    cudaGetSymbolAddress((void**)&p_bsu,   g_bsu);
    cudaGetSymbolAddress((void**)&p_bsi,   g_bsi);
    cudaGetSymbolAddress((void**)&p_nbru,  g_nbru);
    cudaGetSymbolAddress((void**)&p_nbri,  g_nbri);

    // ---- CSR build (once; reused by both layers) ----
    zero_kernel<<<512, 256>>>((float4*)p_degu, (size_t)NU / 4);
    zero_kernel<<<128, 256>>>((float4*)p_degi, (size_t)NI / 4);
    count_kernel<<<(NE + 255) / 256, 256>>>(esrc, edst, p_degu, p_degi);

    int nbu = (NU + 1023) / 1024;   // 489
    int nbi = (NI + 1023) / 1024;   // 98
    scan_block_k<<<nbu, 1024>>>(p_degu, p_offu, p_bsu, NU);
    scan_block_k<<<nbi, 1024>>>(p_degi, p_offi, p_bsi, NI);
    scan_sums_k<<<1, 512>>>(p_bsu, nbu);
    scan_sums_k<<<1, 512>>>(p_bsi, nbi);
    add_off_k<<<(NU + 1024) / 1024, 1024>>>(p_offu, p_curu, p_bsu, NU, NE);
    add_off_k<<<(NI + 1024) / 1024, 1024>>>(p_offi, p_curi, p_bsi, NI, NE);
    build_csr_k<<<(NE + 255) / 256, 256>>>(esrc, edst, p_curu, p_curi, p_nbru, p_nbri);

    // ---- fp16 user embedding table + item input projection ----
    cast_f2h<<<2048, 256>>>((const float4*)user_emb, (uint2*)p_uemb16, (size_t)NU * D / 4);
    item_linear2<<<(NI + 63) / 64, 256>>>(item_x, item_w, item_b, p_xitem);

    // ---- layer 1 ----
    agg_csr_h<<<((size_t)NI * 8 + 255) / 256, 256>>>(p_uemb16, p_offi, p_nbri, p_acci, NI);
    agg_csr_h<<<((size_t)NU * 8 + 255) / 256, 256>>>(p_xitem,  p_offu, p_nbru, p_accu, NU);
    node_update_mma<true><<<(NU + 63) / 64, 256>>>(p_accu, p_offu, p_uemb16,
                                                   Wl1_iu, Wr1_iu, b1_iu, p_hu, NU);
    node_update_mma<true><<<(NI + 63) / 64, 256>>>(p_acci, p_offi, p_xitem,
                                                   Wl1_ui, Wr1_ui, b1_ui, p_hi, NI);

    // ---- layer 2 ----
    agg_csr_h<<<((size_t)NI * 8 + 255) / 256, 256>>>(p_hu, p_offi, p_nbri, p_acci, NI);
    agg_csr_h<<<((size_t)NU * 8 + 255) / 256, 256>>>(p_hi, p_offu, p_nbru, p_accu, NU);
    node_update_mma<false><<<(NU + 63) / 64, 256>>>(p_accu, p_offu, p_hu,
                                                    Wl2_iu, Wr2_iu, b2_iu, p_hu2, NU);
    node_update_mma<false><<<(NI + 63) / 64, 256>>>(p_acci, p_offi, p_hi,
                                                    Wl2_ui, Wr2_ui, b2_ui, p_hi2, NI);

    // ---- predictor ----
    dot_kernel8<<<((size_t)EL * 8 + 255) / 256, 256>>>(p_hu2, p_hi2, lsrc, ldst, out);
}